// round 7
// baseline (speedup 1.0000x reference)
#include <cuda_runtime.h>
#include <cuda_bf16.h>

// HGNN forward, single kernel. Grid (256 graphs x 4 e-quarters), 128 threads.
//   Per block: 12 hyperedges of one graph.
//   M[e,d]  = (1/32) * sum_v H[v,e]*x[v,d]
//   ED[e,f] = relu(sum_d M[e,d]*W[f,d] + b[f])  -> h_e
//   partial c -> Cscratch; LAST quarter-block per graph (threadfence +
//   atomic counter) sums the 4 partials in fixed order and writes c.
// Output buffer: [ c (B*D) | h_e (B*E*D) ]
//
// R7: R6's separate 64-block reduce kernel measured 4.1us (pure launch/tail
// overhead). Fused last-block reduction removes that launch entirely.

constexpr int V   = 8192;
constexpr int E   = 48;
constexpr int D   = 64;
constexpr int B   = 256;
constexpr int NPG = V / B;        // 32 nodes per graph
constexpr int EQN = 4;            // e-quarters
constexpr int EPB = E / EQN;      // 12 edges per block
constexpr int NT  = 128;
constexpr int WS  = 68;           // W shared row stride (floats)

__device__ float Cscratch[EQN * B * D];   // partial-c scratch
__device__ int   Ctr[B];                  // arrival counters (zero-init; reset by last block)

__global__ __launch_bounds__(NT, 8) void hgnn_main_kernel(
    const float* __restrict__ x,     // (V, D)
    const float* __restrict__ Hm,    // (V, E)
    const float* __restrict__ W,     // (D, D) row-major [f][d]
    const float* __restrict__ bias,  // (D,)
    float* __restrict__ out)         // [c | h_e]
{
    __shared__ float Ht[EPB * NPG];   // transposed H slice (1.5 KB)
    __shared__ float Ws[D * WS];      // W rows, stride 68 (17 KB)
    __shared__ float Ms[EPB * D];     // (3 KB)
    __shared__ float Sv[EPB];
    __shared__ float Bs[D];
    __shared__ float Cp[4][D];
    __shared__ int   isLast;

    const int b  = blockIdx.x;
    const int eq = blockIdx.y;
    const int t  = threadIdx.x;

    // ---- stage H slice transposed: Ht[e*32+v] = H[v, eq*12+e] ----
    {
        const float* hb = Hm + (size_t)b * NPG * E + eq * EPB;
        if (t < NPG * 3) {                       // 96 float4 loads
            int v = t / 3, g = t - (t / 3) * 3;
            float4 h = *(const float4*)(hb + v * E + g * 4);
            int e = g * 4;
            Ht[(e + 0) * NPG + v] = h.x;
            Ht[(e + 1) * NPG + v] = h.y;
            Ht[(e + 2) * NPG + v] = h.z;
            Ht[(e + 3) * NPG + v] = h.w;
        }
        // ---- stage W rows into Ws[f*68 + d] (coalesced LDG.128) ----
        #pragma unroll
        for (int i = t; i < D * D / 4; i += NT) {
            float4 w = ((const float4*)W)[i];
            int f = i >> 4, d4 = (i & 15) * 4;
            *(float4*)&Ws[f * WS + d4] = w;
        }
        if (t < D) Bs[t] = bias[t];
    }
    __syncthreads();

    // ---- s[e] = sum_v Ht[e,v] ----
    if (t < EPB) {
        const float4* hr = (const float4*)&Ht[t * NPG];
        float a0 = 0.f, a1 = 0.f;
        #pragma unroll
        for (int k = 0; k < NPG / 8; k++) {
            float4 h0 = hr[2 * k], h1 = hr[2 * k + 1];
            a0 += h0.x + h0.y + h0.z + h0.w;
            a1 += h1.x + h1.y + h1.z + h1.w;
        }
        Sv[t] = a0 + a1;
    }

    // ---- phase 1: M[e,f] ;  f = t&63, qq = t>>6, e = j*2+qq ----
    {
        const int f = t & 63, qq = t >> 6;
        float macc[6];
        #pragma unroll
        for (int j = 0; j < 6; j++) macc[j] = 0.f;

        #pragma unroll
        for (int vc = 0; vc < 2; vc++) {
            float xr[16];
            const float* xg = x + (size_t)b * NPG * D + (vc * 16) * D + f;
            #pragma unroll
            for (int v = 0; v < 16; v++) xr[v] = xg[v * D];   // coalesced

            #pragma unroll
            for (int j = 0; j < 6; j++) {
                int e = j * 2 + qq;
                const float4* hr = (const float4*)&Ht[e * NPG + vc * 16]; // bcast
                #pragma unroll
                for (int k = 0; k < 4; k++) {
                    float4 h = hr[k];
                    macc[j] = fmaf(h.x, xr[4 * k + 0], macc[j]);
                    macc[j] = fmaf(h.y, xr[4 * k + 1], macc[j]);
                    macc[j] = fmaf(h.z, xr[4 * k + 2], macc[j]);
                    macc[j] = fmaf(h.w, xr[4 * k + 3], macc[j]);
                }
            }
        }
        #pragma unroll
        for (int j = 0; j < 6; j++)
            Ms[(j * 2 + qq) * D + f] = macc[j] * (1.0f / NPG);
    }
    __syncthreads();

    // ---- phase 2: 2D tile, u = t&31, es = t>>5; f0 = u, f1 = u+32 ----
    {
        const int u = t & 31, es = t >> 5;
        float acc0[3], acc1[3];
        #pragma unroll
        for (int j = 0; j < 3; j++) { acc0[j] = Bs[u]; acc1[j] = Bs[u + 32]; }

        #pragma unroll
        for (int dc = 0; dc < 4; dc++) {
            float4 wa[4], wb[4];
            const float4* wra = (const float4*)&Ws[u * WS + dc * 16];
            const float4* wrb = (const float4*)&Ws[(u + 32) * WS + dc * 16];
            #pragma unroll
            for (int k = 0; k < 4; k++) { wa[k] = wra[k]; wb[k] = wrb[k]; }

            #pragma unroll
            for (int j = 0; j < 3; j++) {
                int e = j * 4 + es;
                const float4* mr = (const float4*)&Ms[e * D + dc * 16]; // bcast
                #pragma unroll
                for (int k = 0; k < 4; k++) {
                    float4 m = mr[k];
                    acc0[j] = fmaf(m.x, wa[k].x, acc0[j]);
                    acc0[j] = fmaf(m.y, wa[k].y, acc0[j]);
                    acc0[j] = fmaf(m.z, wa[k].z, acc0[j]);
                    acc0[j] = fmaf(m.w, wa[k].w, acc0[j]);
                    acc1[j] = fmaf(m.x, wb[k].x, acc1[j]);
                    acc1[j] = fmaf(m.y, wb[k].y, acc1[j]);
                    acc1[j] = fmaf(m.z, wb[k].z, acc1[j]);
                    acc1[j] = fmaf(m.w, wb[k].w, acc1[j]);
                }
            }
        }

        // relu, h_e store, c fold
        float c0 = 0.f, c1 = 0.f;
        float* he = out + (size_t)B * D + ((size_t)b * E + eq * EPB) * D;
        #pragma unroll
        for (int j = 0; j < 3; j++) {
            int e = j * 4 + es;
            float r0 = fmaxf(acc0[j], 0.f);
            float r1 = fmaxf(acc1[j], 0.f);
            he[e * D + u]      = r0;     // coalesced 128B
            he[e * D + u + 32] = r1;     // coalesced 128B
            float sv = Sv[e];
            c0 = fmaf(sv, r0, c0);
            c1 = fmaf(sv, r1, c1);
        }
        Cp[es][u]      = c0;
        Cp[es][u + 32] = c1;
    }
    __syncthreads();

    // ---- partial c -> scratch; last quarter-block per graph reduces ----
    if (t < D) {
        float c = Cp[0][t] + Cp[1][t] + Cp[2][t] + Cp[3][t];
        Cscratch[(eq * B + b) * D + t] = c;
    }
    __threadfence();
    __syncthreads();
    if (t == 0) {
        int old = atomicAdd(&Ctr[b], 1);
        isLast = (old == EQN - 1);
    }
    __syncthreads();
    if (isLast) {
        __threadfence();                 // acquire partials from peer blocks
        if (t < D) {
            float s = Cscratch[b * D + t]
                    + Cscratch[(B + b) * D + t]
                    + Cscratch[(2 * B + b) * D + t]
                    + Cscratch[(3 * B + b) * D + t];
            out[b * D + t] = s * (1.0f / (NPG * E));
        }
        __syncthreads();
        if (t == 0) Ctr[b] = 0;          // clean for next graph replay
    }
}

extern "C" void kernel_launch(void* const* d_in, const int* in_sizes, int n_in,
                              void* d_out, int out_size) {
    const float* x    = (const float*)d_in[0];   // (V,D)
    const float* Hm   = (const float*)d_in[1];   // (V,E)
    const float* W    = (const float*)d_in[2];   // (D,D)
    const float* bias = (const float*)d_in[3];   // (D,)
    float* out = (float*)d_out;

    dim3 grid(B, EQN);
    hgnn_main_kernel<<<grid, NT>>>(x, Hm, W, bias, out);
}

// round 8
// speedup vs baseline: 1.0445x; 1.0445x over previous
#include <cuda_runtime.h>
#include <cuda_bf16.h>

// HGNN forward, single kernel. Grid (256 graphs x 4 e-quarters), 128 threads.
//   Per block: 12 hyperedges of one graph.
//   M[e,d]  = (1/32) * sum_v H[v,e]*x[v,d]
//   ED[e,f] = relu(sum_d M[e,d]*W[f,d] + b[f])  -> h_e
//   partial c -> Cscratch (stcg); last quarter-block per graph detected via
//   atom.add.acq_rel.gpu counter (NO __threadfence -> no CCTL.IVALL L1 flush)
//   sums the 4 partials in fixed order and writes c.
// Output buffer: [ c (B*D) | h_e (B*E*D) ]

constexpr int V   = 8192;
constexpr int E   = 48;
constexpr int D   = 64;
constexpr int B   = 256;
constexpr int NPG = V / B;        // 32 nodes per graph
constexpr int EQN = 4;            // e-quarters
constexpr int EPB = E / EQN;      // 12 edges per block
constexpr int NT  = 128;
constexpr int WS  = 68;           // W shared row stride (floats)

__device__ float Cscratch[EQN * B * D];   // partial-c scratch (L2-resident via stcg)
__device__ int   Ctr[B];                  // arrival counters (zero-init; reset by last block)

__global__ __launch_bounds__(NT, 8) void hgnn_main_kernel(
    const float* __restrict__ x,     // (V, D)
    const float* __restrict__ Hm,    // (V, E)
    const float* __restrict__ W,     // (D, D) row-major [f][d]
    const float* __restrict__ bias,  // (D,)
    float* __restrict__ out)         // [c | h_e]
{
    __shared__ float Ht[EPB * NPG];   // transposed H slice (1.5 KB)
    __shared__ float Ws[D * WS];      // W rows, stride 68 (17 KB)
    __shared__ float Ms[EPB * D];     // (3 KB)
    __shared__ float Sv[EPB];
    __shared__ float Bs[D];
    __shared__ float Cp[4][D];
    __shared__ int   isLast;

    const int b  = blockIdx.x;
    const int eq = blockIdx.y;
    const int t  = threadIdx.x;

    // ---- stage H slice transposed: Ht[e*32+v] = H[v, eq*12+e] ----
    {
        const float* hb = Hm + (size_t)b * NPG * E + eq * EPB;
        if (t < NPG * 3) {                       // 96 float4 loads
            int v = t / 3, g = t - (t / 3) * 3;
            float4 h = *(const float4*)(hb + v * E + g * 4);
            int e = g * 4;
            Ht[(e + 0) * NPG + v] = h.x;
            Ht[(e + 1) * NPG + v] = h.y;
            Ht[(e + 2) * NPG + v] = h.z;
            Ht[(e + 3) * NPG + v] = h.w;
        }
        // ---- stage W rows into Ws[f*68 + d] (coalesced LDG.128) ----
        #pragma unroll
        for (int i = t; i < D * D / 4; i += NT) {
            float4 w = ((const float4*)W)[i];
            int f = i >> 4, d4 = (i & 15) * 4;
            *(float4*)&Ws[f * WS + d4] = w;
        }
        if (t < D) Bs[t] = bias[t];
    }
    __syncthreads();

    // ---- s[e] = sum_v Ht[e,v] ----
    if (t < EPB) {
        const float4* hr = (const float4*)&Ht[t * NPG];
        float a0 = 0.f, a1 = 0.f;
        #pragma unroll
        for (int k = 0; k < NPG / 8; k++) {
            float4 h0 = hr[2 * k], h1 = hr[2 * k + 1];
            a0 += h0.x + h0.y + h0.z + h0.w;
            a1 += h1.x + h1.y + h1.z + h1.w;
        }
        Sv[t] = a0 + a1;
    }

    // ---- phase 1: M[e,f] ;  f = t&63, qq = t>>6, e = j*2+qq ----
    {
        const int f = t & 63, qq = t >> 6;
        float macc[6];
        #pragma unroll
        for (int j = 0; j < 6; j++) macc[j] = 0.f;

        #pragma unroll
        for (int vc = 0; vc < 2; vc++) {
            float xr[16];
            const float* xg = x + (size_t)b * NPG * D + (vc * 16) * D + f;
            #pragma unroll
            for (int v = 0; v < 16; v++) xr[v] = xg[v * D];   // coalesced

            #pragma unroll
            for (int j = 0; j < 6; j++) {
                int e = j * 2 + qq;
                const float4* hr = (const float4*)&Ht[e * NPG + vc * 16]; // bcast
                #pragma unroll
                for (int k = 0; k < 4; k++) {
                    float4 h = hr[k];
                    macc[j] = fmaf(h.x, xr[4 * k + 0], macc[j]);
                    macc[j] = fmaf(h.y, xr[4 * k + 1], macc[j]);
                    macc[j] = fmaf(h.z, xr[4 * k + 2], macc[j]);
                    macc[j] = fmaf(h.w, xr[4 * k + 3], macc[j]);
                }
            }
        }
        #pragma unroll
        for (int j = 0; j < 6; j++)
            Ms[(j * 2 + qq) * D + f] = macc[j] * (1.0f / NPG);
    }
    __syncthreads();

    // ---- phase 2: 2D tile, u = t&31, es = t>>5; f0 = u, f1 = u+32 ----
    {
        const int u = t & 31, es = t >> 5;
        float acc0[3], acc1[3];
        #pragma unroll
        for (int j = 0; j < 3; j++) { acc0[j] = Bs[u]; acc1[j] = Bs[u + 32]; }

        #pragma unroll
        for (int dc = 0; dc < 4; dc++) {
            float4 wa[4], wb[4];
            const float4* wra = (const float4*)&Ws[u * WS + dc * 16];
            const float4* wrb = (const float4*)&Ws[(u + 32) * WS + dc * 16];
            #pragma unroll
            for (int k = 0; k < 4; k++) { wa[k] = wra[k]; wb[k] = wrb[k]; }

            #pragma unroll
            for (int j = 0; j < 3; j++) {
                int e = j * 4 + es;
                const float4* mr = (const float4*)&Ms[e * D + dc * 16]; // bcast
                #pragma unroll
                for (int k = 0; k < 4; k++) {
                    float4 m = mr[k];
                    acc0[j] = fmaf(m.x, wa[k].x, acc0[j]);
                    acc0[j] = fmaf(m.y, wa[k].y, acc0[j]);
                    acc0[j] = fmaf(m.z, wa[k].z, acc0[j]);
                    acc0[j] = fmaf(m.w, wa[k].w, acc0[j]);
                    acc1[j] = fmaf(m.x, wb[k].x, acc1[j]);
                    acc1[j] = fmaf(m.y, wb[k].y, acc1[j]);
                    acc1[j] = fmaf(m.z, wb[k].z, acc1[j]);
                    acc1[j] = fmaf(m.w, wb[k].w, acc1[j]);
                }
            }
        }

        // relu, h_e store, c fold
        float c0 = 0.f, c1 = 0.f;
        float* he = out + (size_t)B * D + ((size_t)b * E + eq * EPB) * D;
        #pragma unroll
        for (int j = 0; j < 3; j++) {
            int e = j * 4 + es;
            float r0 = fmaxf(acc0[j], 0.f);
            float r1 = fmaxf(acc1[j], 0.f);
            he[e * D + u]      = r0;     // coalesced 128B
            he[e * D + u + 32] = r1;     // coalesced 128B
            float sv = Sv[e];
            c0 = fmaf(sv, r0, c0);
            c1 = fmaf(sv, r1, c1);
        }
        Cp[es][u]      = c0;
        Cp[es][u + 32] = c1;
    }
    __syncthreads();

    // ---- partial c -> L2 scratch (stcg, no L1 involvement) ----
    if (t < D) {
        float c = Cp[0][t] + Cp[1][t] + Cp[2][t] + Cp[3][t];
        __stcg(&Cscratch[(eq * B + b) * D + t], c);
    }
    __syncthreads();   // cta edge: all partial stores happen-before t0's release

    if (t == 0) {
        int old;
        asm volatile("atom.add.acq_rel.gpu.global.s32 %0, [%1], 1;"
                     : "=r"(old) : "l"(&Ctr[b]) : "memory");
        isLast = (old == EQN - 1);
    }
    __syncthreads();   // cta edge: t0's acquire happens-before consumer loads

    if (isLast) {
        if (t < D) {
            float s = __ldcg(&Cscratch[b * D + t])
                    + __ldcg(&Cscratch[(B + b) * D + t])
                    + __ldcg(&Cscratch[(2 * B + b) * D + t])
                    + __ldcg(&Cscratch[(3 * B + b) * D + t]);
            out[b * D + t] = s * (1.0f / (NPG * E));
        }
        if (t == 0) Ctr[b] = 0;          // clean for next replay
    }
}

extern "C" void kernel_launch(void* const* d_in, const int* in_sizes, int n_in,
                              void* d_out, int out_size) {
    const float* x    = (const float*)d_in[0];   // (V,D)
    const float* Hm   = (const float*)d_in[1];   // (V,E)
    const float* W    = (const float*)d_in[2];   // (D,D)
    const float* bias = (const float*)d_in[3];   // (D,)
    float* out = (float*)d_out;

    dim3 grid(B, EQN);
    hgnn_main_kernel<<<grid, NT>>>(x, Hm, W, bias, out);
}